// round 7
// baseline (speedup 1.0000x reference)
#include <cuda_runtime.h>

// Problem constants
#define H 512
#define W 512
#define HW (H * W)
#define NC 48                 // 16 batch * 3 channels
#define OH 171
#define OW 171
#define TOTAL (NC * OH * OW)  // 1,403,568 output pixels
#define NBLOCKS 1184          // 148 SMs * 8 queued (6 resident @40regs) — best-measured DRAM feed

__device__ float        g_partial = 0.0f;
__device__ unsigned int g_count   = 0;

__global__ void __launch_bounds__(256, 6) ssim_kernel(
    const float* __restrict__ img1,
    const float* __restrict__ img2,
    const float* __restrict__ window,
    float* __restrict__ out)
{
    const float C1 = 0.0001f;   // 0.01^2
    const float C2 = 0.0009f;   // 0.03^2

    // 3x3 gaussian window (identical per channel) — broadcast, L1-resident
    float w[9];
    #pragma unroll
    for (int i = 0; i < 9; i++) w[i] = __ldg(window + i);

    float acc = 0.0f;

    const int stride = NBLOCKS * 256;
    for (int idx = blockIdx.x * blockDim.x + threadIdx.x; idx < TOTAL; idx += stride) {
        const int ox    = idx % OW;
        const int t     = idx / OW;
        const int oy    = t % OH;
        const int plane = t / OH;

        const int ix = 3 * ox - 1;
        const int iy = 3 * oy - 1;

        const float* __restrict__ q1 = img1 + (size_t)plane * HW + iy * W + ix;
        const float* __restrict__ q2 = img2 + (size_t)plane * HW + iy * W + ix;

        // Tap validity: only row/col index -1 can be out of bounds
        // (high side: 3*170+1 = 511 always in range). Uniform predicated
        // loads — no divergent boundary path.
        const bool cok = (ix >= 0);   // col tap c==0 valid?
        const bool rok = (iy >= 0);   // row tap r==0 valid?

        float a[9], b[9];
        #pragma unroll
        for (int r = 0; r < 3; r++) {
            #pragma unroll
            for (int c = 0; c < 3; c++) {
                const bool ok = (r > 0 || rok) && (c > 0 || cok);
                a[r * 3 + c] = ok ? __ldg(q1 + r * W + c) : 0.0f;
            }
        }
        #pragma unroll
        for (int r = 0; r < 3; r++) {
            #pragma unroll
            for (int c = 0; c < 3; c++) {
                const bool ok = (r > 0 || rok) && (c > 0 || cok);
                b[r * 3 + c] = ok ? __ldg(q2 + r * W + c) : 0.0f;
            }
        }

        float mu1 = 0.f, mu2 = 0.f, s11 = 0.f, s22 = 0.f, s12 = 0.f;
        #pragma unroll
        for (int k = 0; k < 9; k++) {
            const float wa = w[k] * a[k];
            const float wb = w[k] * b[k];
            mu1 += wa;
            mu2 += wb;
            s11 = fmaf(wa, a[k], s11);
            s22 = fmaf(wb, b[k], s22);
            s12 = fmaf(wa, b[k], s12);
        }

        const float m11 = mu1 * mu1;
        const float m22 = mu2 * mu2;
        const float m12 = mu1 * mu2;
        const float v1  = s11 - m11;   // sigma1_sq
        const float v2  = s22 - m22;   // sigma2_sq
        const float v12 = s12 - m12;   // sigma12

        const float num = (2.0f * m12 + C1) * (2.0f * v12 + C2);
        const float den = (m11 + m22 + C1) * (v1 + v2 + C2);
        acc += __fdividef(num, den);
    }

    // ---- block reduction: warp shuffle -> smem -> warp0 -> one atomic ----
    #pragma unroll
    for (int o = 16; o > 0; o >>= 1)
        acc += __shfl_down_sync(0xffffffffu, acc, o);

    __shared__ float wsum[8];
    const int lane = threadIdx.x & 31;
    const int wid  = threadIdx.x >> 5;
    if (lane == 0) wsum[wid] = acc;
    __syncthreads();

    if (wid == 0) {
        acc = (lane < 8) ? wsum[lane] : 0.0f;
        #pragma unroll
        for (int o = 4; o > 0; o >>= 1)
            acc += __shfl_down_sync(0xffffffffu, acc, o);
        if (lane == 0)
            atomicAdd(&g_partial, acc * (1.0f / (float)TOTAL));
    }

    // ---- last block publishes result, resets scratch (graph-replay safe) ----
    __shared__ bool is_last;
    if (threadIdx.x == 0) {
        __threadfence();
        const unsigned prev = atomicAdd(&g_count, 1u);
        is_last = (prev == (unsigned)(gridDim.x - 1));
    }
    __syncthreads();
    if (is_last && threadIdx.x == 0) {
        *out      = g_partial;
        g_partial = 0.0f;
        g_count   = 0;
    }
}

extern "C" void kernel_launch(void* const* d_in, const int* in_sizes, int n_in,
                              void* d_out, int out_size)
{
    const float* img1   = (const float*)d_in[0];
    const float* img2   = (const float*)d_in[1];
    const float* window = (const float*)d_in[2];
    float* out = (float*)d_out;

    ssim_kernel<<<NBLOCKS, 256>>>(img1, img2, window, out);
}

// round 8
// speedup vs baseline: 1.2424x; 1.2424x over previous
#include <cuda_runtime.h>

// Problem constants
#define H 512
#define W 512
#define HW (H * W)
#define NC 48                 // 16 batch * 3 channels
#define OH 171
#define OW 171
#define TOTAL (NC * OH * OW)  // 1,403,568 output pixels
#define IW 170                // interior ox/oy in 1..170
#define NI (NC * IW * IW)     // 1,387,200 interior pixels
#define NE (NC * (OH + IW))   // 16,368 edge pixels (oy==0 row + ox==0 col)
#define NBLOCKS 888           // 148 SMs * 6 resident — one clean wave

__device__ float        g_partial = 0.0f;
__device__ unsigned int g_count   = 0;

__global__ void __launch_bounds__(256, 6) ssim_kernel(
    const float* __restrict__ img1,
    const float* __restrict__ img2,
    const float* __restrict__ window,
    float* __restrict__ out)
{
    const float C1 = 0.0001f;   // 0.01^2
    const float C2 = 0.0009f;   // 0.03^2

    // 3x3 gaussian window (identical per channel) — broadcast, L1-resident
    float w[9];
    #pragma unroll
    for (int i = 0; i < 9; i++) w[i] = __ldg(window + i);

    float acc = 0.0f;
    const int gtid   = blockIdx.x * blockDim.x + threadIdx.x;
    const int stride = NBLOCKS * 256;

    // ---- hot loop: interior pixels only (ox,oy in 1..170) — branch-free ----
    for (int idx = gtid; idx < NI; idx += stride) {
        const int ox    = 1 + idx % IW;
        const int t     = idx / IW;
        const int oy    = 1 + t % IW;
        const int plane = t / IW;

        const int ix = 3 * ox - 1;   // >= 2
        const int iy = 3 * oy - 1;   // >= 2, high side 511 max

        const float* __restrict__ q1 = img1 + (size_t)plane * HW + iy * W + ix;
        const float* __restrict__ q2 = img2 + (size_t)plane * HW + iy * W + ix;

        float a[9], b[9];
        #pragma unroll
        for (int r = 0; r < 3; r++)
            #pragma unroll
            for (int c = 0; c < 3; c++)
                a[r * 3 + c] = __ldg(q1 + r * W + c);
        #pragma unroll
        for (int r = 0; r < 3; r++)
            #pragma unroll
            for (int c = 0; c < 3; c++)
                b[r * 3 + c] = __ldg(q2 + r * W + c);

        float mu1 = 0.f, mu2 = 0.f, s11 = 0.f, s22 = 0.f, s12 = 0.f;
        #pragma unroll
        for (int k = 0; k < 9; k++) {
            const float wa = w[k] * a[k];
            const float wb = w[k] * b[k];
            mu1 += wa;
            mu2 += wb;
            s11 = fmaf(wa, a[k], s11);
            s22 = fmaf(wb, b[k], s22);
            s12 = fmaf(wa, b[k], s12);
        }

        const float m11 = mu1 * mu1;
        const float m22 = mu2 * mu2;
        const float m12 = mu1 * mu2;
        const float num = (2.0f * m12 + C1) * (2.0f * (s12 - m12) + C2);
        const float den = (m11 + m22 + C1) * ((s11 - m11) + (s22 - m22) + C2);
        acc += __fdividef(num, den);
    }

    // ---- cold loop: edge pixels (oy==0 full row, then ox==0 column) ----
    for (int e = gtid; e < NE; e += stride) {
        const int plane = e / (OH + IW);
        const int r0    = e % (OH + IW);
        int ox, oy;
        if (r0 < OH) { oy = 0;        ox = r0; }
        else         { ox = 0;        oy = r0 - IW; }   // oy = 1..170

        const int ix = 3 * ox - 1;
        const int iy = 3 * oy - 1;
        const float* __restrict__ p1 = img1 + (size_t)plane * HW;
        const float* __restrict__ p2 = img2 + (size_t)plane * HW;

        float mu1 = 0.f, mu2 = 0.f, s11 = 0.f, s22 = 0.f, s12 = 0.f;
        #pragma unroll
        for (int r = 0; r < 3; r++) {
            #pragma unroll
            for (int c = 0; c < 3; c++) {
                const int row = iy + r;
                const int col = ix + c;
                const bool ok = (row >= 0) && (col >= 0);
                const float a = ok ? __ldg(p1 + row * W + col) : 0.0f;
                const float b = ok ? __ldg(p2 + row * W + col) : 0.0f;
                const float wt = w[r * 3 + c];
                const float wa = wt * a;
                const float wb = wt * b;
                mu1 += wa;
                mu2 += wb;
                s11 = fmaf(wa, a, s11);
                s22 = fmaf(wb, b, s22);
                s12 = fmaf(wa, b, s12);
            }
        }

        const float m11 = mu1 * mu1;
        const float m22 = mu2 * mu2;
        const float m12 = mu1 * mu2;
        const float num = (2.0f * m12 + C1) * (2.0f * (s12 - m12) + C2);
        const float den = (m11 + m22 + C1) * ((s11 - m11) + (s22 - m22) + C2);
        acc += __fdividef(num, den);
    }

    // ---- block reduction: warp shuffle -> smem -> warp0 -> one atomic ----
    #pragma unroll
    for (int o = 16; o > 0; o >>= 1)
        acc += __shfl_down_sync(0xffffffffu, acc, o);

    __shared__ float wsum[8];
    const int lane = threadIdx.x & 31;
    const int wid  = threadIdx.x >> 5;
    if (lane == 0) wsum[wid] = acc;
    __syncthreads();

    if (wid == 0) {
        acc = (lane < 8) ? wsum[lane] : 0.0f;
        #pragma unroll
        for (int o = 4; o > 0; o >>= 1)
            acc += __shfl_down_sync(0xffffffffu, acc, o);
        if (lane == 0)
            atomicAdd(&g_partial, acc * (1.0f / (float)TOTAL));
    }

    // ---- last block publishes result, resets scratch (graph-replay safe) ----
    __shared__ bool is_last;
    if (threadIdx.x == 0) {
        __threadfence();
        const unsigned prev = atomicAdd(&g_count, 1u);
        is_last = (prev == (unsigned)(gridDim.x - 1));
    }
    __syncthreads();
    if (is_last && threadIdx.x == 0) {
        *out      = g_partial;
        g_partial = 0.0f;
        g_count   = 0;
    }
}

extern "C" void kernel_launch(void* const* d_in, const int* in_sizes, int n_in,
                              void* d_out, int out_size)
{
    const float* img1   = (const float*)d_in[0];
    const float* img2   = (const float*)d_in[1];
    const float* window = (const float*)d_in[2];
    float* out = (float*)d_out;

    ssim_kernel<<<NBLOCKS, 256>>>(img1, img2, window, out);
}

// round 9
// speedup vs baseline: 1.2543x; 1.0096x over previous
#include <cuda_runtime.h>

// Problem constants
#define H 512
#define W 512
#define HW (H * W)
#define NC 48                 // 16 batch * 3 channels
#define OH 171
#define OW 171
#define TOTAL (NC * OH * OW)  // 1,403,568 output pixels
#define IW 170                // interior ox/oy in 1..170
#define NI (NC * IW * IW)     // 1,387,200 interior pixels
#define NE (NC * (OH + IW))   // 16,368 edge pixels (oy==0 row + ox==0 col)
#define NBLOCKS 1184          // 148 SMs * 8 queued (6 resident @40regs): 2-deep block queue

__device__ float        g_partial = 0.0f;
__device__ unsigned int g_count   = 0;

__global__ void __launch_bounds__(256, 6) ssim_kernel(
    const float* __restrict__ img1,
    const float* __restrict__ img2,
    const float* __restrict__ window,
    float* __restrict__ out)
{
    const float C1 = 0.0001f;   // 0.01^2
    const float C2 = 0.0009f;   // 0.03^2

    // 3x3 gaussian window (identical per channel) — broadcast, L1-resident
    float w[9];
    #pragma unroll
    for (int i = 0; i < 9; i++) w[i] = __ldg(window + i);

    float acc = 0.0f;
    const int gtid   = blockIdx.x * blockDim.x + threadIdx.x;
    const int stride = NBLOCKS * 256;

    // ---- hot loop: interior pixels only (ox,oy in 1..170) — branch-free ----
    for (int idx = gtid; idx < NI; idx += stride) {
        const int ox    = 1 + idx % IW;
        const int t     = idx / IW;
        const int oy    = 1 + t % IW;
        const int plane = t / IW;

        const int ix = 3 * ox - 1;   // >= 2
        const int iy = 3 * oy - 1;   // >= 2, high side 511 max

        const float* __restrict__ q1 = img1 + (size_t)plane * HW + iy * W + ix;
        const float* __restrict__ q2 = img2 + (size_t)plane * HW + iy * W + ix;

        float a[9], b[9];
        #pragma unroll
        for (int r = 0; r < 3; r++)
            #pragma unroll
            for (int c = 0; c < 3; c++)
                a[r * 3 + c] = __ldg(q1 + r * W + c);
        #pragma unroll
        for (int r = 0; r < 3; r++)
            #pragma unroll
            for (int c = 0; c < 3; c++)
                b[r * 3 + c] = __ldg(q2 + r * W + c);

        float mu1 = 0.f, mu2 = 0.f, s11 = 0.f, s22 = 0.f, s12 = 0.f;
        #pragma unroll
        for (int k = 0; k < 9; k++) {
            const float wa = w[k] * a[k];
            const float wb = w[k] * b[k];
            mu1 += wa;
            mu2 += wb;
            s11 = fmaf(wa, a[k], s11);
            s22 = fmaf(wb, b[k], s22);
            s12 = fmaf(wa, b[k], s12);
        }

        const float m11 = mu1 * mu1;
        const float m22 = mu2 * mu2;
        const float m12 = mu1 * mu2;
        const float num = (2.0f * m12 + C1) * (2.0f * (s12 - m12) + C2);
        const float den = (m11 + m22 + C1) * ((s11 - m11) + (s22 - m22) + C2);
        acc += __fdividef(num, den);
    }

    // ---- cold loop: edge pixels (oy==0 full row, then ox==0 column) ----
    for (int e = gtid; e < NE; e += stride) {
        const int plane = e / (OH + IW);
        const int r0    = e % (OH + IW);
        int ox, oy;
        if (r0 < OH) { oy = 0;        ox = r0; }
        else         { ox = 0;        oy = r0 - IW; }   // oy = 1..170

        const int ix = 3 * ox - 1;
        const int iy = 3 * oy - 1;
        const float* __restrict__ p1 = img1 + (size_t)plane * HW;
        const float* __restrict__ p2 = img2 + (size_t)plane * HW;

        float mu1 = 0.f, mu2 = 0.f, s11 = 0.f, s22 = 0.f, s12 = 0.f;
        #pragma unroll
        for (int r = 0; r < 3; r++) {
            #pragma unroll
            for (int c = 0; c < 3; c++) {
                const int row = iy + r;
                const int col = ix + c;
                const bool ok = (row >= 0) && (col >= 0);
                const float a = ok ? __ldg(p1 + row * W + col) : 0.0f;
                const float b = ok ? __ldg(p2 + row * W + col) : 0.0f;
                const float wt = w[r * 3 + c];
                const float wa = wt * a;
                const float wb = wt * b;
                mu1 += wa;
                mu2 += wb;
                s11 = fmaf(wa, a, s11);
                s22 = fmaf(wb, b, s22);
                s12 = fmaf(wa, b, s12);
            }
        }

        const float m11 = mu1 * mu1;
        const float m22 = mu2 * mu2;
        const float m12 = mu1 * mu2;
        const float num = (2.0f * m12 + C1) * (2.0f * (s12 - m12) + C2);
        const float den = (m11 + m22 + C1) * ((s11 - m11) + (s22 - m22) + C2);
        acc += __fdividef(num, den);
    }

    // ---- block reduction: warp shuffle -> smem -> warp0 -> one atomic ----
    #pragma unroll
    for (int o = 16; o > 0; o >>= 1)
        acc += __shfl_down_sync(0xffffffffu, acc, o);

    __shared__ float wsum[8];
    const int lane = threadIdx.x & 31;
    const int wid  = threadIdx.x >> 5;
    if (lane == 0) wsum[wid] = acc;
    __syncthreads();

    if (wid == 0) {
        acc = (lane < 8) ? wsum[lane] : 0.0f;
        #pragma unroll
        for (int o = 4; o > 0; o >>= 1)
            acc += __shfl_down_sync(0xffffffffu, acc, o);
        if (lane == 0)
            atomicAdd(&g_partial, acc * (1.0f / (float)TOTAL));
    }

    // ---- last block publishes result, resets scratch (graph-replay safe) ----
    __shared__ bool is_last;
    if (threadIdx.x == 0) {
        __threadfence();
        const unsigned prev = atomicAdd(&g_count, 1u);
        is_last = (prev == (unsigned)(gridDim.x - 1));
    }
    __syncthreads();
    if (is_last && threadIdx.x == 0) {
        *out      = g_partial;
        g_partial = 0.0f;
        g_count   = 0;
    }
}

extern "C" void kernel_launch(void* const* d_in, const int* in_sizes, int n_in,
                              void* d_out, int out_size)
{
    const float* img1   = (const float*)d_in[0];
    const float* img2   = (const float*)d_in[1];
    const float* window = (const float*)d_in[2];
    float* out = (float*)d_out;

    ssim_kernel<<<NBLOCKS, 256>>>(img1, img2, window, out);
}